// round 12
// baseline (speedup 1.0000x reference)
#include <cuda_runtime.h>
#include <cuda_bf16.h>
#include <math.h>
#include <stdint.h>

// ---------------- problem constants ----------------
#define NN     200000
#define NEDGE  800000
#define CBB    480
#define CT     484
#define FDIM   128
#define NPIX   (FDIM*FDIM)
#define HID    128
#define KIN    488

// ---------------- smem layout (bytes) ----------------
#define TILE1    10240                 // 128 rows x 40 bf16 (80B stride)
#define RAW_OFF  0                     // 128 nodes x 4 pixels x 128B = 65536
#define A1H_OFF  65536                 // A tile hi (10240)
#define A1L_OFF  75776                 // A tile lo (10240)
#define B1_OFF(b) (86016 + (b)*2*TILE1)  // hi +0, lo +TILE1; two buffers
#define A2_STR   272                   // h1 tile row stride bytes
#define A2H_OFF  0                     // overlaps RAW+A1 (GEMM2 phase only)
#define A2L_OFF  34816
#define PQ_OFF   126976                // int4[128]
#define WQ_OFF   129024                // float4[128]
#define SQ_OFF   131072                // float4[128]
#define SMEM_BYTES 133120

// ---------------- device scratch ----------------
__device__ float g_ft[(size_t)NPIX * CT + 32];  // (pixel, channel) fp32 feature map (+pad for chunk-15 overread)
__device__ __nv_bfloat16 g_W1h[128*512];        // [n][k'=512] hi
__device__ __nv_bfloat16 g_W1l[128*512];        // lo
__device__ __nv_bfloat16 g_W2h[128*128];        // [n][k=128] hi
__device__ __nv_bfloat16 g_W2l[128*128];
__device__ int g_deg[NN];
__device__ int g_maxdeg;
__device__ int g_e64;

// ---------------- helpers ----------------
__device__ __forceinline__ void cp16(void* s, const void* g) {
    unsigned ss = (unsigned)__cvta_generic_to_shared(s);
    asm volatile("cp.async.cg.shared.global [%0], [%1], 16;" :: "r"(ss), "l"(g));
}
#define CP_COMMIT() asm volatile("cp.async.commit_group;")
#define CP_WAIT0()  asm volatile("cp.async.wait_group 0;" ::: "memory")

__device__ __forceinline__ uint32_t sm32(const void* p) {
    return (uint32_t)__cvta_generic_to_shared(p);
}
__device__ __forceinline__ void ldsm4(uint32_t* r, uint32_t a) {
    asm volatile("ldmatrix.sync.aligned.m8n8.x4.shared.b16 {%0,%1,%2,%3}, [%4];"
        : "=r"(r[0]), "=r"(r[1]), "=r"(r[2]), "=r"(r[3]) : "r"(a));
}
__device__ __forceinline__ void mma16816(float* d, const uint32_t* a, uint32_t b0, uint32_t b1) {
    asm("mma.sync.aligned.m16n8k16.row.col.f32.bf16.bf16.f32 "
        "{%0,%1,%2,%3}, {%4,%5,%6,%7}, {%8,%9}, {%0,%1,%2,%3};"
        : "+f"(d[0]), "+f"(d[1]), "+f"(d[2]), "+f"(d[3])
        : "r"(a[0]), "r"(a[1]), "r"(a[2]), "r"(a[3]), "r"(b0), "r"(b1));
}

__device__ __forceinline__ void b1fill(int c, char* dstH, int tid) {
    int r = tid >> 1, seg = (tid & 1) * 2;
    const char* sh = (const char*)g_W1h + r * 1024 + c * 64 + seg * 16;
    const char* sl = (const char*)g_W1l + r * 1024 + c * 64 + seg * 16;
    char* dh = dstH + r * 80 + seg * 16;
    char* dl = dstH + TILE1 + r * 80 + seg * 16;
    cp16(dh, sh); cp16(dh + 16, sh + 16);
    cp16(dl, sl); cp16(dl + 16, sl + 16);
}
__device__ __forceinline__ void b2fill(int c, char* dstH, int tid) {
    int r = tid >> 1, seg = (tid & 1) * 2;
    const char* sh = (const char*)g_W2h + r * 256 + c * 64 + seg * 16;
    const char* sl = (const char*)g_W2l + r * 256 + c * 64 + seg * 16;
    char* dh = dstH + r * 80 + seg * 16;
    char* dl = dstH + TILE1 + r * 80 + seg * 16;
    cp16(dh, sh); cp16(dh + 16, sh + 16);
    cp16(dl, sl); cp16(dl + 16, sl + 16);
}

// fire-and-forget raw gather of chunk c: per node, 4 pixel-rows of 128B (32 ch)
__device__ __forceinline__ void raw_issue(const int4* __restrict__ Pq, int tid, char* raw, int c) {
    const int n = tid >> 1, half = tid & 1;
    int4 q = Pq[n];
    const int p0 = half * 2;
    const int o0 = half ? q.z : q.x;
    const int o1 = half ? q.w : q.y;
    const char* s0 = (const char*)(g_ft + o0 + c * 32);
    const char* s1 = (const char*)(g_ft + o1 + c * 32);
    char* d0 = raw + n * 512 + p0 * 128;
    char* d1 = d0 + 128;
    #pragma unroll
    for (int g2 = 0; g2 < 8; g2++) {
        cp16(d0 + g2 * 16, s0 + g2 * 16);
        cp16(d1 + g2 * 16, s1 + g2 * 16);
    }
}

// combine raw pixels -> bf16 hi/lo A tile (smem -> smem, no gmem latency)
__device__ __forceinline__ void combine(const float4* __restrict__ Wq, const float4* __restrict__ Sq,
        const char* __restrict__ raw, char* __restrict__ aH, char* __restrict__ aL,
        int warp, int lane, int c) {
    const int kp2 = (lane & 15) * 2;
    const int k = c * 32 + kp2;
    const int kofs = (lane & 15) * 4;
    const int wp = warp * 2 + (lane >> 4);
    #pragma unroll
    for (int it = 0; it < 8; it++) {
        const int m = it * 16 + wp;
        float v0, v1;
        if (k < CT) {
            const char* rb = raw + m * 512 + kp2 * 4;
            float2 f0 = *(const float2*)(rb);
            float2 f1 = *(const float2*)(rb + 128);
            float2 f2 = *(const float2*)(rb + 256);
            float2 f3 = *(const float2*)(rb + 384);
            float4 w = Wq[m];
            v0 = w.x * f0.x + w.y * f1.x + w.z * f2.x + w.w * f3.x;
            v1 = w.x * f0.y + w.y * f1.y + w.z * f2.y + w.w * f3.y;
        } else if (k == 484) { float4 s = Sq[m]; v0 = s.x; v1 = s.y; }
        else if (k == 486)   { float4 s = Sq[m]; v0 = s.z; v1 = s.w; }
        else { v0 = 0.0f; v1 = 0.0f; }
        uint32_t hw, lw;
        asm("cvt.rn.bf16x2.f32 %0, %1, %2;" : "=r"(hw) : "f"(v1), "f"(v0));
        float l0 = v0 - __uint_as_float(hw << 16);
        float l1 = v1 - __uint_as_float(hw & 0xffff0000u);
        asm("cvt.rn.bf16x2.f32 %0, %1, %2;" : "=r"(lw) : "f"(l1), "f"(l0));
        *(uint32_t*)(aH + m * 80 + kofs) = hw;
        *(uint32_t*)(aL + m * 80 + kofs) = lw;
    }
}

// ---------------- prep kernels ----------------
#define PB_Z   782
#define PB_W1  (PB_Z + 128)
#define PB_W2  (PB_W1 + 64)
#define PB_T   (PB_W2 + 8192)

__global__ void k_prep(const int* __restrict__ e,
                       const float* __restrict__ W1, const float* __restrict__ W2,
                       const float* __restrict__ bb, const float* __restrict__ seg) {
    int bx = blockIdx.x, tid = threadIdx.x;
    if (bx < PB_Z) {
        int i = bx * 256 + tid;
        if (i < NN) g_deg[i] = 0;
        if (bx == 0 && tid < 32) {
            int nz = (e[2 * tid + 1] != 0) ? 1 : 0;
            unsigned m = __ballot_sync(0xffffffffu, nz);
            if (tid == 0) { g_e64 = (m == 0u) ? 1 : 0; g_maxdeg = 0; }
        }
    } else if (bx < PB_W1) {
        int n = bx - PB_Z;
        #pragma unroll
        for (int it = 0; it < 2; it++) {
            int r = it * 256 + tid;
            int col;
            if      (r < CT)   col = r + 2;
            else if (r == 484) col = 0;
            else if (r == 485) col = 1;
            else if (r == 486) col = 486;
            else if (r == 487) col = 487;
            else               col = -1;
            float v = (col >= 0) ? W1[n * KIN + col] : 0.0f;
            __nv_bfloat16 h = __float2bfloat16(v);
            g_W1h[n * 512 + r] = h;
            g_W1l[n * 512 + r] = __float2bfloat16(v - __bfloat162float(h));
        }
    } else if (bx < PB_W2) {
        int n = (bx - PB_W1) * 2 + (tid >> 7), k = tid & 127;
        float v = W2[n * HID + k];
        __nv_bfloat16 h = __float2bfloat16(v);
        g_W2h[n * 128 + k] = h;
        g_W2l[n * 128 + k] = __float2bfloat16(v - __bfloat162float(h));
    } else {
        __shared__ float t[32][33];
        int i = bx - PB_W2;
        int c0 = (i & 15) * 32, p0 = (i >> 4) * 32;
        int tx = tid & 31, ty = tid >> 5;    // 32 x 8
        #pragma unroll
        for (int q = 0; q < 4; q++) {
            int c = c0 + ty + q * 8;
            float v = 0.0f;
            if (c < CT)
                v = (c < CBB) ? bb[(size_t)c * NPIX + p0 + tx]
                              : seg[(size_t)(c - CBB) * NPIX + p0 + tx];
            t[ty + q * 8][tx] = v;
        }
        __syncthreads();
        #pragma unroll
        for (int q = 0; q < 4; q++) {
            int p = p0 + ty + q * 8;
            int c = c0 + tx;
            if (c < CT) g_ft[(size_t)p * CT + c] = t[tx][ty + q * 8];
        }
    }
}

__global__ void k_degree(const void* __restrict__ eptr) {
    const int total = 2 * NEDGE;
    const bool is64 = (g_e64 != 0);
    const long long* __restrict__ e64 = (const long long*)eptr;
    const int* __restrict__ e32 = (const int*)eptr;
    for (int i = blockIdx.x * blockDim.x + threadIdx.x; i < total; i += gridDim.x * blockDim.x) {
        int idx = is64 ? (int)e64[i] : e32[i];
        atomicAdd(&g_deg[idx], 1);
    }
}

__global__ void k_max() {
    int i = blockIdx.x * blockDim.x + threadIdx.x;
    int v = (i < NN) ? g_deg[i] : 0;
    #pragma unroll
    for (int o = 16; o > 0; o >>= 1) v = max(v, __shfl_down_sync(0xffffffffu, v, o));
    if ((threadIdx.x & 31) == 0) atomicMax(&g_maxdeg, v);
}

// ---------------- main: cp.async raw gather + bf16-split mma.sync ----------------
__global__ void __launch_bounds__(256, 1) k_main(
    const float* __restrict__ verts,
    const float* __restrict__ b1,
    const float* __restrict__ b2,
    float* __restrict__ out)
{
    extern __shared__ char smem[];
    int4*   Pq = (int4*)(smem + PQ_OFF);
    float4* Wq = (float4*)(smem + WQ_OFF);
    float4* Sq = (float4*)(smem + SQ_OFF);
    char*   raw = smem + RAW_OFF;

    const int tid = threadIdx.x;
    const int m0 = blockIdx.x * 128;

    // per-node params
    if (tid < 128) {
        int node = min(m0 + tid, NN - 1);
        float vx = verts[2 * node], vy = verts[2 * node + 1];
        float ix = vx * (127.0f / 512.0f), iy = vy * (127.0f / 512.0f);
        float fx = floorf(ix), fy = floorf(iy);
        float wx = ix - fx, wy = iy - fy;
        int x0 = min(max((int)fx, 0), FDIM - 1);
        int x1 = min(x0 + 1, FDIM - 1);
        int y0 = min(max((int)fy, 0), FDIM - 1);
        int y1 = min(y0 + 1, FDIM - 1);
        Pq[tid] = make_int4((y0 * FDIM + x0) * CT, (y0 * FDIM + x1) * CT,
                            (y1 * FDIM + x0) * CT, (y1 * FDIM + x1) * CT);
        Wq[tid] = make_float4((1.0f - wx) * (1.0f - wy), wx * (1.0f - wy),
                              (1.0f - wx) * wy, wx * wy);
        float dg = (float)g_deg[node] / ((float)g_maxdeg + 1e-6f);
        float dx = fminf(vx, 512.0f - vx), dy = fminf(vy, 512.0f - vy);
        Sq[tid] = make_float4(vx * (1.0f / 512.0f), vy * (1.0f / 512.0f),
                              dg, fminf(dx, dy) * (1.0f / 256.0f));
    }
    __syncthreads();

    const int warp = tid >> 5, lane = tid & 31;
    const int g  = lane >> 2, tc = (lane & 3) * 2;
    const int wM = (warp & 3) * 32, wN = (warp >> 2) * 64;
    // ldmatrix lane selectors
    const int lrow  = (lane & 7) + ((lane >> 3) & 1) * 8;   // A: matrix row
    const int lcolA = (lane >> 4) * 16;                     // A: k-half byte sel
    const int lbrow = lane & 7;                             // B: n row
    const int lbcol = ((lane >> 3) & 1) * 16;               // B: k-half byte sel
    const int lbsel = (lane >> 4);                          // B: 0=hi tile, 1=lo tile

    float acc[2][8][4];
    #pragma unroll
    for (int a = 0; a < 2; a++)
        #pragma unroll
        for (int b = 0; b < 8; b++)
            #pragma unroll
            for (int c = 0; c < 4; c++) acc[a][b][c] = 0.0f;

    // -------- prologue: raw(0) + B(0) via cp.async --------
    raw_issue(Pq, tid, raw, 0);
    b1fill(0, smem + B1_OFF(0), tid);
    CP_COMMIT();
    CP_WAIT0();
    __syncthreads();

    // ================= GEMM1: 16 chunks of 32 =================
    #pragma unroll 1
    for (int c = 0; c < 16; c++) {
        // combine raw(c) -> A tile (smem only, no gmem latency on the chain)
        combine(Wq, Sq, raw, smem + A1H_OFF, smem + A1L_OFF, warp, lane, c);
        __syncthreads();                       // A ready; raw consumed

        if (c < 15) {
            raw_issue(Pq, tid, raw, c + 1);    // fire-and-forget, overlaps math
            b1fill(c + 1, smem + B1_OFF((c + 1) & 1), tid);
        } else {
            b2fill(0, smem + B1_OFF(0), tid);  // prefetch W2 chunk 0
        }
        CP_COMMIT();

        char* Ah = smem + A1H_OFF;
        char* Al = smem + A1L_OFF;
        char* Bh = smem + B1_OFF(c & 1);
        #pragma unroll
        for (int k16 = 0; k16 < 2; k16++) {
            uint32_t ah0[4], ah1[4], al0[4], al1[4];
            ldsm4(ah0, sm32(Ah + (wM +      lrow) * 80 + k16 * 32 + lcolA));
            ldsm4(ah1, sm32(Ah + (wM + 16 + lrow) * 80 + k16 * 32 + lcolA));
            ldsm4(al0, sm32(Al + (wM +      lrow) * 80 + k16 * 32 + lcolA));
            ldsm4(al1, sm32(Al + (wM + 16 + lrow) * 80 + k16 * 32 + lcolA));
            #pragma unroll
            for (int nb = 0; nb < 8; nb++) {
                uint32_t b[4];
                ldsm4(b, sm32(Bh + (wN + nb * 8 + lbrow) * 80 + k16 * 32 + lbcol + lbsel * TILE1));
                mma16816(acc[0][nb], ah0, b[0], b[1]);
                mma16816(acc[0][nb], ah0, b[2], b[3]);
                mma16816(acc[0][nb], al0, b[0], b[1]);
                mma16816(acc[1][nb], ah1, b[0], b[1]);
                mma16816(acc[1][nb], ah1, b[2], b[3]);
                mma16816(acc[1][nb], al1, b[0], b[1]);
            }
        }
        CP_WAIT0();
        __syncthreads();
    }

    // -------- epilogue 1: h1 = relu(D1 + b1) -> bf16 hi/lo smem tile (overlaps raw region) --------
    {
        char* A2h = smem + A2H_OFF;
        char* A2l = smem + A2L_OFF;
        #pragma unroll
        for (int mb = 0; mb < 2; mb++) {
            int row = wM + mb * 16 + g;
            #pragma unroll
            for (int nb = 0; nb < 8; nb++) {
                int col = wN + nb * 8 + tc;
                float2 bb = *(const float2*)(b1 + col);
                float v0 = fmaxf(acc[mb][nb][0] + bb.x, 0.0f);
                float v1 = fmaxf(acc[mb][nb][1] + bb.y, 0.0f);
                float v2 = fmaxf(acc[mb][nb][2] + bb.x, 0.0f);
                float v3 = fmaxf(acc[mb][nb][3] + bb.y, 0.0f);
                uint32_t h0, l0w, h1w, l1w;
                asm("cvt.rn.bf16x2.f32 %0, %1, %2;" : "=r"(h0) : "f"(v1), "f"(v0));
                float r0 = v0 - __uint_as_float(h0 << 16);
                float r1 = v1 - __uint_as_float(h0 & 0xffff0000u);
                asm("cvt.rn.bf16x2.f32 %0, %1, %2;" : "=r"(l0w) : "f"(r1), "f"(r0));
                asm("cvt.rn.bf16x2.f32 %0, %1, %2;" : "=r"(h1w) : "f"(v3), "f"(v2));
                float r2 = v2 - __uint_as_float(h1w << 16);
                float r3 = v3 - __uint_as_float(h1w & 0xffff0000u);
                asm("cvt.rn.bf16x2.f32 %0, %1, %2;" : "=r"(l1w) : "f"(r3), "f"(r2));
                *(uint32_t*)(A2h + row * A2_STR + col * 2) = h0;
                *(uint32_t*)(A2l + row * A2_STR + col * 2) = l0w;
                *(uint32_t*)(A2h + (row + 8) * A2_STR + col * 2) = h1w;
                *(uint32_t*)(A2l + (row + 8) * A2_STR + col * 2) = l1w;
            }
        }
    }
    #pragma unroll
    for (int a = 0; a < 2; a++)
        #pragma unroll
        for (int b = 0; b < 8; b++)
            #pragma unroll
            for (int c = 0; c < 4; c++) acc[a][b][c] = 0.0f;
    __syncthreads();

    // ================= GEMM2: 4 chunks of 32 (double-buffered B) =================
    #pragma unroll 1
    for (int c2 = 0; c2 < 4; c2++) {
        if (c2 < 3) {
            b2fill(c2 + 1, smem + B1_OFF((c2 + 1) & 1), tid);
            CP_COMMIT();
        }
        char* A2h = smem + A2H_OFF + c2 * 64;
        char* A2l = smem + A2L_OFF + c2 * 64;
        char* Bh = smem + B1_OFF(c2 & 1);
        #pragma unroll
        for (int k16 = 0; k16 < 2; k16++) {
            uint32_t ah0[4], ah1[4], al0[4], al1[4];
            ldsm4(ah0, sm32(A2h + (wM +      lrow) * A2_STR + k16 * 32 + lcolA));
            ldsm4(ah1, sm32(A2h + (wM + 16 + lrow) * A2_STR + k16 * 32 + lcolA));
            ldsm4(al0, sm32(A2l + (wM +      lrow) * A2_STR + k16 * 32 + lcolA));
            ldsm4(al1, sm32(A2l + (wM + 16 + lrow) * A2_STR + k16 * 32 + lcolA));
            #pragma unroll
            for (int nb = 0; nb < 8; nb++) {
                uint32_t b[4];
                ldsm4(b, sm32(Bh + (wN + nb * 8 + lbrow) * 80 + k16 * 32 + lbcol + lbsel * TILE1));
                mma16816(acc[0][nb], ah0, b[0], b[1]);
                mma16816(acc[0][nb], ah0, b[2], b[3]);
                mma16816(acc[0][nb], al0, b[0], b[1]);
                mma16816(acc[1][nb], ah1, b[0], b[1]);
                mma16816(acc[1][nb], ah1, b[2], b[3]);
                mma16816(acc[1][nb], al1, b[0], b[1]);
            }
        }
        CP_WAIT0();
        __syncthreads();
    }

    // -------- epilogue 2: out = relu(D2 + b2) --------
    #pragma unroll
    for (int mb = 0; mb < 2; mb++) {
        int m1 = m0 + wM + mb * 16 + g;
        int m2 = m1 + 8;
        #pragma unroll
        for (int nb = 0; nb < 8; nb++) {
            int col = wN + nb * 8 + tc;
            float2 bb = *(const float2*)(b2 + col);
            if (m1 < NN) {
                float2 v = make_float2(fmaxf(acc[mb][nb][0] + bb.x, 0.0f),
                                       fmaxf(acc[mb][nb][1] + bb.y, 0.0f));
                *(float2*)(out + (size_t)m1 * HID + col) = v;
            }
            if (m2 < NN) {
                float2 v = make_float2(fmaxf(acc[mb][nb][2] + bb.x, 0.0f),
                                       fmaxf(acc[mb][nb][3] + bb.y, 0.0f));
                *(float2*)(out + (size_t)m2 * HID + col) = v;
            }
        }
    }
}

// ---------------- launch ----------------
extern "C" void kernel_launch(void* const* d_in, const int* in_sizes, int n_in,
                              void* d_out, int out_size)
{
    const float* verts = (const float*)d_in[0];
    const float* bb    = (const float*)d_in[1];
    const float* seg   = (const float*)d_in[2];
    const void*  edges = d_in[3];
    const float* W1    = (const float*)d_in[4];
    const float* b1    = (const float*)d_in[5];
    const float* W2    = (const float*)d_in[6];
    const float* b2    = (const float*)d_in[7];
    float* out = (float*)d_out;

    k_prep<<<PB_T, 256>>>((const int*)edges, W1, W2, bb, seg);
    k_degree<<<2048, 256>>>(edges);
    k_max<<<(NN + 255) / 256, 256>>>();

    cudaFuncSetAttribute(k_main, cudaFuncAttributeMaxDynamicSharedMemorySize, SMEM_BYTES);
    k_main<<<(NN + 127) / 128, 256, SMEM_BYTES>>>(verts, b1, b2, out);
}

// round 13
// speedup vs baseline: 1.9715x; 1.9715x over previous
#include <cuda_runtime.h>
#include <math.h>
#include <stdint.h>

// ---------------- problem constants ----------------
#define NN     200000
#define NEDGE  800000
#define CBB    480
#define CT     484
#define FDIM   128
#define NPIX   (FDIM*FDIM)
#define HID    128
#define KIN    488

// ---------------- smem layout (bytes) ----------------
#define A1_STR   144                   // 36 floats: frag banks 4g+tr -> conflict-free
#define A1_OFF(b) ((b)*18432)          // 128 x 144
#define B1_OFF(b) (36864 + (b)*18432)
#define A2_OFF   0                     // h1 tile, overlaps A1/B1 after GEMM1
#define A2_STR   528                   // 132 floats
#define B2_OFF   73728                 // 128 x 144 single buffer
#define B2_STR   144
#define PQ_OFF   92160                 // int4[128]
#define WQ_OFF   94208                 // float4[128]
#define SQ_OFF   96256                 // float4[128]
#define SMEM_BYTES 98304               // x2 CTAs = 192KB < 228KB

// ---------------- device scratch ----------------
__device__ float g_ft[(size_t)NPIX * CT + 32];  // (pixel, channel) fp32 feature map
__device__ float g_W1t[128*512];                // [n][k'=512] tf32-rounded, permuted, zero-padded
__device__ float g_W2t[128*128];                // [n][k=128] tf32-rounded
__device__ int g_deg[NN];
__device__ int g_maxdeg;
__device__ int g_e64;

// ---------------- helpers ----------------
__device__ __forceinline__ void cp16(void* s, const void* g) {
    unsigned ss = (unsigned)__cvta_generic_to_shared(s);
    asm volatile("cp.async.cg.shared.global [%0], [%1], 16;" :: "r"(ss), "l"(g));
}
#define CP_COMMIT() asm volatile("cp.async.commit_group;")
#define CP_WAIT0()  asm volatile("cp.async.wait_group 0;" ::: "memory")

__device__ __forceinline__ uint32_t to_tf32(float v) {
    uint32_t r;
    asm("cvt.rna.tf32.f32 %0, %1;" : "=r"(r) : "f"(v));
    return r;
}
__device__ __forceinline__ void mma_tf32(float* d, const uint32_t* a, uint32_t b0, uint32_t b1) {
    asm("mma.sync.aligned.m16n8k8.row.col.f32.tf32.tf32.f32 "
        "{%0,%1,%2,%3}, {%4,%5,%6,%7}, {%8,%9}, {%0,%1,%2,%3};"
        : "+f"(d[0]), "+f"(d[1]), "+f"(d[2]), "+f"(d[3])
        : "r"(a[0]), "r"(a[1]), "r"(a[2]), "r"(a[3]), "r"(b0), "r"(b1));
}
// A fragment m16k8: a0=(row,col) a1=(row+8,col) a2=(row,col+4) a3=(row+8,col+4)
__device__ __forceinline__ void ldA(uint32_t* a, const char* A, int row, int col, int str) {
    const char* p = A + row * str + col * 4;
    a[0] = *(const uint32_t*)p;
    a[1] = *(const uint32_t*)(p + 8 * str);
    a[2] = *(const uint32_t*)(p + 16);
    a[3] = *(const uint32_t*)(p + 8 * str + 16);
}

__device__ __forceinline__ void bld_issue(const int4* __restrict__ Pq, int m, int k, float2* f) {
    if (k < CT) {
        int4 q = Pq[m];
        const float* __restrict__ ft = g_ft;
        f[0] = *(const float2*)(ft + q.x + k);
        f[1] = *(const float2*)(ft + q.y + k);
        f[2] = *(const float2*)(ft + q.z + k);
        f[3] = *(const float2*)(ft + q.w + k);
    }
}
__device__ __forceinline__ void bld_store(const float4* __restrict__ Wq, const float4* __restrict__ Sq,
        int m, int k, const float2* f, char* aDst, int kofs) {
    float v0, v1;
    if (k < CT) {
        float4 w = Wq[m];
        v0 = w.x * f[0].x + w.y * f[1].x + w.z * f[2].x + w.w * f[3].x;
        v1 = w.x * f[0].y + w.y * f[1].y + w.z * f[2].y + w.w * f[3].y;
    } else if (k == 484) { float4 s = Sq[m]; v0 = s.x; v1 = s.y; }
    else if (k == 486)   { float4 s = Sq[m]; v0 = s.z; v1 = s.w; }
    else { v0 = 0.0f; v1 = 0.0f; }
    uint2 t = make_uint2(to_tf32(v0), to_tf32(v1));
    *(uint2*)(aDst + m * A1_STR + kofs) = t;
}

__device__ __forceinline__ void b1fill(int c, char* dst, int tid) {
    #pragma unroll
    for (int i = 0; i < 4; i++) {
        int id = tid * 4 + i;            // 0..1023 granules of 16B
        int r = id >> 3, g8 = id & 7;
        cp16(dst + r * A1_STR + g8 * 16, (const char*)g_W1t + r * 2048 + c * 128 + g8 * 16);
    }
}
__device__ __forceinline__ void b2fill(int c, char* dst, int tid) {
    #pragma unroll
    for (int i = 0; i < 4; i++) {
        int id = tid * 4 + i;
        int r = id >> 3, g8 = id & 7;
        cp16(dst + r * B2_STR + g8 * 16, (const char*)g_W2t + r * 512 + c * 128 + g8 * 16);
    }
}

// ---------------- prep kernels ----------------
#define PB_Z   782
#define PB_W1  (PB_Z + 128)
#define PB_W2  (PB_W1 + 64)
#define PB_T   (PB_W2 + 8192)

__global__ void k_prep(const int* __restrict__ e,
                       const float* __restrict__ W1, const float* __restrict__ W2,
                       const float* __restrict__ bb, const float* __restrict__ seg) {
    int bx = blockIdx.x, tid = threadIdx.x;
    if (bx < PB_Z) {
        int i = bx * 256 + tid;
        if (i < NN) g_deg[i] = 0;
        if (bx == 0 && tid < 32) {
            int nz = (e[2 * tid + 1] != 0) ? 1 : 0;
            unsigned m = __ballot_sync(0xffffffffu, nz);
            if (tid == 0) { g_e64 = (m == 0u) ? 1 : 0; g_maxdeg = 0; }
        }
    } else if (bx < PB_W1) {
        int n = bx - PB_Z;
        #pragma unroll
        for (int it = 0; it < 2; it++) {
            int r = it * 256 + tid;
            int col;
            if      (r < CT)   col = r + 2;
            else if (r == 484) col = 0;
            else if (r == 485) col = 1;
            else if (r == 486) col = 486;
            else if (r == 487) col = 487;
            else               col = -1;
            float v = (col >= 0) ? W1[n * KIN + col] : 0.0f;
            uint32_t t; asm("cvt.rna.tf32.f32 %0, %1;" : "=r"(t) : "f"(v));
            g_W1t[n * 512 + r] = __uint_as_float(t);
        }
    } else if (bx < PB_W2) {
        int n = (bx - PB_W1) * 2 + (tid >> 7), k = tid & 127;
        float v = W2[n * HID + k];
        uint32_t t; asm("cvt.rna.tf32.f32 %0, %1;" : "=r"(t) : "f"(v));
        g_W2t[n * 128 + k] = __uint_as_float(t);
    } else {
        __shared__ float t[32][33];
        int i = bx - PB_W2;
        int c0 = (i & 15) * 32, p0 = (i >> 4) * 32;
        int tx = tid & 31, ty = tid >> 5;    // 32 x 8
        #pragma unroll
        for (int q = 0; q < 4; q++) {
            int c = c0 + ty + q * 8;
            float v = 0.0f;
            if (c < CT)
                v = (c < CBB) ? bb[(size_t)c * NPIX + p0 + tx]
                              : seg[(size_t)(c - CBB) * NPIX + p0 + tx];
            t[ty + q * 8][tx] = v;
        }
        __syncthreads();
        #pragma unroll
        for (int q = 0; q < 4; q++) {
            int p = p0 + ty + q * 8;
            int c = c0 + tx;
            if (c < CT) g_ft[(size_t)p * CT + c] = t[tx][ty + q * 8];
        }
    }
}

__global__ void k_degree(const void* __restrict__ eptr) {
    const int total = 2 * NEDGE;
    const bool is64 = (g_e64 != 0);
    const long long* __restrict__ e64 = (const long long*)eptr;
    const int* __restrict__ e32 = (const int*)eptr;
    for (int i = blockIdx.x * blockDim.x + threadIdx.x; i < total; i += gridDim.x * blockDim.x) {
        int idx = is64 ? (int)e64[i] : e32[i];
        atomicAdd(&g_deg[idx], 1);
    }
}

__global__ void k_max() {
    int i = blockIdx.x * blockDim.x + threadIdx.x;
    int v = (i < NN) ? g_deg[i] : 0;
    #pragma unroll
    for (int o = 16; o > 0; o >>= 1) v = max(v, __shfl_down_sync(0xffffffffu, v, o));
    if ((threadIdx.x & 31) == 0) atomicMax(&g_maxdeg, v);
}

// ---------------- main: gather + single-pass tf32 mma.sync MLP ----------------
__global__ void __launch_bounds__(256, 2) k_main(
    const float* __restrict__ verts,
    const float* __restrict__ b1,
    const float* __restrict__ b2,
    float* __restrict__ out)
{
    extern __shared__ char smem[];
    int4*   Pq = (int4*)(smem + PQ_OFF);
    float4* Wq = (float4*)(smem + WQ_OFF);
    float4* Sq = (float4*)(smem + SQ_OFF);

    const int tid = threadIdx.x;
    const int m0 = blockIdx.x * 128;

    // per-node params
    if (tid < 128) {
        int node = min(m0 + tid, NN - 1);
        float vx = verts[2 * node], vy = verts[2 * node + 1];
        float ix = vx * (127.0f / 512.0f), iy = vy * (127.0f / 512.0f);
        float fx = floorf(ix), fy = floorf(iy);
        float wx = ix - fx, wy = iy - fy;
        int x0 = min(max((int)fx, 0), FDIM - 1);
        int x1 = min(x0 + 1, FDIM - 1);
        int y0 = min(max((int)fy, 0), FDIM - 1);
        int y1 = min(y0 + 1, FDIM - 1);
        Pq[tid] = make_int4((y0 * FDIM + x0) * CT, (y0 * FDIM + x1) * CT,
                            (y1 * FDIM + x0) * CT, (y1 * FDIM + x1) * CT);
        Wq[tid] = make_float4((1.0f - wx) * (1.0f - wy), wx * (1.0f - wy),
                              (1.0f - wx) * wy, wx * wy);
        float dg = (float)g_deg[node] / ((float)g_maxdeg + 1e-6f);
        float dx = fminf(vx, 512.0f - vx), dy = fminf(vy, 512.0f - vy);
        Sq[tid] = make_float4(vx * (1.0f / 512.0f), vy * (1.0f / 512.0f),
                              dg, fminf(dx, dy) * (1.0f / 256.0f));
    }
    __syncthreads();

    const int warp = tid >> 5, lane = tid & 31;
    const int g  = lane >> 2, tr = lane & 3, tc = tr * 2;
    const int wM = (warp & 3) * 32, wN = (warp >> 2) * 64;
    const int wp   = warp * 2 + (lane >> 4);      // builder m sub-index (0..15)
    const int kp2  = (lane & 15) * 2;             // builder k-pair within chunk
    const int kofs = (lane & 15) * 8;             // builder store byte offset (uint2)

    float acc[2][8][4];
    #pragma unroll
    for (int a = 0; a < 2; a++)
        #pragma unroll
        for (int b = 0; b < 8; b++)
            #pragma unroll
            for (int c = 0; c < 4; c++) acc[a][b][c] = 0.0f;

    // -------- prologue: build A(0), fill B(0) --------
    b1fill(0, smem + B1_OFF(0), tid);
    CP_COMMIT();
    #pragma unroll
    for (int it = 0; it < 8; it++) {
        float2 f[4];
        int m = it * 16 + wp;
        bld_issue(Pq, m, kp2, f);
        bld_store(Wq, Sq, m, kp2, f, smem + A1_OFF(0), kofs);
    }
    CP_WAIT0();
    __syncthreads();

    // ================= GEMM1: 16 chunks of 32 =================
    #pragma unroll 1
    for (int c = 0; c < 16; c++) {
        const char* A = smem + A1_OFF(c & 1);
        const char* B = smem + B1_OFF(c & 1);
        char* nA = smem + A1_OFF((c + 1) & 1);
        const bool more = (c < 15);

        if (more) b1fill(c + 1, smem + B1_OFF((c + 1) & 1), tid);
        CP_COMMIT();

        const int kn = (c + 1) * 32 + kp2;
        #pragma unroll
        for (int s = 0; s < 4; s++) {                 // k8 segments
            float2 f0[4], f1[4];
            const int mA = s * 32 + wp, mB = s * 32 + 16 + wp;
            if (more) { bld_issue(Pq, mA, kn, f0); bld_issue(Pq, mB, kn, f1); }

            uint32_t a0[4], a1[4];
            ldA(a0, A, wM + g,      s * 8 + tr, A1_STR);
            ldA(a1, A, wM + 16 + g, s * 8 + tr, A1_STR);
            #pragma unroll
            for (int nb = 0; nb < 8; nb++) {
                const char* bp = B + (wN + nb * 8 + g) * A1_STR + (s * 8 + tr) * 4;
                uint32_t b0 = *(const uint32_t*)bp;
                uint32_t b1r = *(const uint32_t*)(bp + 16);
                mma_tf32(acc[0][nb], a0, b0, b1r);
                mma_tf32(acc[1][nb], a1, b0, b1r);
            }
            if (more) { bld_store(Wq, Sq, mA, kn, f0, nA, kofs); bld_store(Wq, Sq, mB, kn, f1, nA, kofs); }
        }
        CP_WAIT0();
        __syncthreads();
    }

    // -------- epilogue 1: h1 = relu(D1 + b1) -> tf32 smem tile A2 --------
    {
        char* A2 = smem + A2_OFF;
        #pragma unroll
        for (int mb = 0; mb < 2; mb++) {
            int row = wM + mb * 16 + g;
            #pragma unroll
            for (int nb = 0; nb < 8; nb++) {
                int col = wN + nb * 8 + tc;
                float2 bb = *(const float2*)(b1 + col);
                float v0 = fmaxf(acc[mb][nb][0] + bb.x, 0.0f);
                float v1 = fmaxf(acc[mb][nb][1] + bb.y, 0.0f);
                float v2 = fmaxf(acc[mb][nb][2] + bb.x, 0.0f);
                float v3 = fmaxf(acc[mb][nb][3] + bb.y, 0.0f);
                *(uint2*)(A2 + row * A2_STR + col * 4)       = make_uint2(to_tf32(v0), to_tf32(v1));
                *(uint2*)(A2 + (row + 8) * A2_STR + col * 4) = make_uint2(to_tf32(v2), to_tf32(v3));
            }
        }
    }
    #pragma unroll
    for (int a = 0; a < 2; a++)
        #pragma unroll
        for (int b = 0; b < 8; b++)
            #pragma unroll
            for (int c = 0; c < 4; c++) acc[a][b][c] = 0.0f;
    __syncthreads();

    // ================= GEMM2: 4 chunks of 32 (single B2 buffer) =================
    #pragma unroll 1
    for (int c2 = 0; c2 < 4; c2++) {
        b2fill(c2, smem + B2_OFF, tid);
        CP_COMMIT(); CP_WAIT0();
        __syncthreads();
        const char* A2 = smem + A2_OFF;
        const char* B = smem + B2_OFF;
        #pragma unroll
        for (int s = 0; s < 4; s++) {
            uint32_t a0[4], a1[4];
            int col = c2 * 32 + s * 8 + tr;
            ldA(a0, A2, wM + g,      col, A2_STR);
            ldA(a1, A2, wM + 16 + g, col, A2_STR);
            #pragma unroll
            for (int nb = 0; nb < 8; nb++) {
                const char* bp = B + (wN + nb * 8 + g) * B2_STR + (s * 8 + tr) * 4;
                uint32_t b0 = *(const uint32_t*)bp;
                uint32_t b1r = *(const uint32_t*)(bp + 16);
                mma_tf32(acc[0][nb], a0, b0, b1r);
                mma_tf32(acc[1][nb], a1, b0, b1r);
            }
        }
        __syncthreads();    // all reads done before next b2fill overwrites
    }

    // -------- epilogue 2: out = relu(D2 + b2) --------
    #pragma unroll
    for (int mb = 0; mb < 2; mb++) {
        int m1 = m0 + wM + mb * 16 + g;
        int m2 = m1 + 8;
        #pragma unroll
        for (int nb = 0; nb < 8; nb++) {
            int col = wN + nb * 8 + tc;
            float2 bb = *(const float2*)(b2 + col);
            if (m1 < NN) {
                float2 v = make_float2(fmaxf(acc[mb][nb][0] + bb.x, 0.0f),
                                       fmaxf(acc[mb][nb][1] + bb.y, 0.0f));
                *(float2*)(out + (size_t)m1 * HID + col) = v;
            }
            if (m2 < NN) {
                float2 v = make_float2(fmaxf(acc[mb][nb][2] + bb.x, 0.0f),
                                       fmaxf(acc[mb][nb][3] + bb.y, 0.0f));
                *(float2*)(out + (size_t)m2 * HID + col) = v;
            }
        }
    }
}

// ---------------- launch ----------------
extern "C" void kernel_launch(void* const* d_in, const int* in_sizes, int n_in,
                              void* d_out, int out_size)
{
    const float* verts = (const float*)d_in[0];
    const float* bb    = (const float*)d_in[1];
    const float* seg   = (const float*)d_in[2];
    const void*  edges = d_in[3];
    const float* W1    = (const float*)d_in[4];
    const float* b1    = (const float*)d_in[5];
    const float* W2    = (const float*)d_in[6];
    const float* b2    = (const float*)d_in[7];
    float* out = (float*)d_out;

    k_prep<<<PB_T, 256>>>((const int*)edges, W1, W2, bb, seg);
    k_degree<<<2048, 256>>>(edges);
    k_max<<<(NN + 255) / 256, 256>>>();

    cudaFuncSetAttribute(k_main, cudaFuncAttributeMaxDynamicSharedMemorySize, SMEM_BYTES);
    k_main<<<(NN + 127) / 128, 256, SMEM_BYTES>>>(verts, b1, b2, out);
}

// round 14
// speedup vs baseline: 2.0734x; 1.0517x over previous
#include <cuda_runtime.h>
#include <math.h>
#include <stdint.h>

// ---------------- problem constants ----------------
#define NN     200000
#define NEDGE  800000
#define CBB    480
#define CT     484
#define FDIM   128
#define NPIX   (FDIM*FDIM)
#define HID    128
#define KIN    488

// ---------------- smem layout (bytes) ----------------
#define A1_STR   144                   // 36 floats -> scalar A-frag LDS conflict-free
#define B1_STR   160                   // 40 floats -> LDS.64 B-frag conflict-free
#define A1_OFF(b) ((b)*18432)          // 2 x 128x144
#define B1_OFF(b) (36864 + (b)*20480)  // 2 x 128x160, ends 77824
#define A2_OFF   0                     // h1 tile (GEMM2 phase), overlaps A1/B1
#define A2_STR   528                   // 132 floats
#define B2_OFF   77824                 // 128x160 single buffer
#define B2_STR   160
#define PQ_OFF   98304                 // int4[128]
#define WQ_OFF   100352                // float4[128]
#define SQ_OFF   102400                // float4[128]
#define SMEM_BYTES 104448              // x2 CTAs = 208896 < 228KB

// ---------------- device scratch ----------------
__device__ float g_ft[(size_t)NPIX * CT + 32];  // (pixel, channel) fp32 feature map
__device__ float g_W1t[128*512];                // [n][k'] tf32, permuted cols + pair-permute
__device__ float g_W2t[128*128];                // [n][k] tf32, pair-permute
__device__ int g_deg[NN];
__device__ int g_maxdeg;
__device__ int g_e64;

// pair-permute within each 8: col j -> pos 2*(j%4) + j/4  => (j, j+4) adjacent
__device__ __forceinline__ int permpos(int r) {
    return (r & ~7) + ((r & 3) << 1) + ((r >> 2) & 1);
}

// ---------------- helpers ----------------
__device__ __forceinline__ void cp16(void* s, const void* g) {
    unsigned ss = (unsigned)__cvta_generic_to_shared(s);
    asm volatile("cp.async.cg.shared.global [%0], [%1], 16;" :: "r"(ss), "l"(g));
}
#define CP_COMMIT() asm volatile("cp.async.commit_group;")
#define CP_WAIT0()  asm volatile("cp.async.wait_group 0;" ::: "memory")

__device__ __forceinline__ uint32_t to_tf32(float v) {
    uint32_t r;
    asm("cvt.rna.tf32.f32 %0, %1;" : "=r"(r) : "f"(v));
    return r;
}
__device__ __forceinline__ void mma_tf32(float* d, const uint32_t* a, uint32_t b0, uint32_t b1) {
    asm("mma.sync.aligned.m16n8k8.row.col.f32.tf32.tf32.f32 "
        "{%0,%1,%2,%3}, {%4,%5,%6,%7}, {%8,%9}, {%0,%1,%2,%3};"
        : "+f"(d[0]), "+f"(d[1]), "+f"(d[2]), "+f"(d[3])
        : "r"(a[0]), "r"(a[1]), "r"(a[2]), "r"(a[3]), "r"(b0), "r"(b1));
}
// A fragment m16k8: a0=(row,col) a1=(row+8,col) a2=(row,col+4) a3=(row+8,col+4)
__device__ __forceinline__ void ldA(uint32_t* a, const char* A, int row, int col, int str) {
    const char* p = A + row * str + col * 4;
    a[0] = *(const uint32_t*)p;
    a[1] = *(const uint32_t*)(p + 8 * str);
    a[2] = *(const uint32_t*)(p + 16);
    a[3] = *(const uint32_t*)(p + 8 * str + 16);
}

// builder: one m, one k-quad (k0..k0+3)
__device__ __forceinline__ void bld_issue4(const int4* __restrict__ Pq, int m, int k0, float4* f) {
    if (k0 < CT) {
        int4 q = Pq[m];
        const float* __restrict__ ft = g_ft;
        f[0] = *(const float4*)(ft + q.x + k0);
        f[1] = *(const float4*)(ft + q.y + k0);
        f[2] = *(const float4*)(ft + q.z + k0);
        f[3] = *(const float4*)(ft + q.w + k0);
    }
}
__device__ __forceinline__ void bld_store4(const float4* __restrict__ Wq, const float4* __restrict__ Sq,
        int m, int k0, const float4* f, char* dst) {
    float4 v;
    if (k0 < CT) {
        float4 w = Wq[m];
        v.x = w.x * f[0].x + w.y * f[1].x + w.z * f[2].x + w.w * f[3].x;
        v.y = w.x * f[0].y + w.y * f[1].y + w.z * f[2].y + w.w * f[3].y;
        v.z = w.x * f[0].z + w.y * f[1].z + w.z * f[2].z + w.w * f[3].z;
        v.w = w.x * f[0].w + w.y * f[1].w + w.z * f[2].w + w.w * f[3].w;
    } else if (k0 == 484) {
        v = Sq[m];                      // k 484..487 = coordx, coordy, deg, dist
    } else {
        v = make_float4(0.f, 0.f, 0.f, 0.f);
    }
    uint4 t = make_uint4(to_tf32(v.x), to_tf32(v.y), to_tf32(v.z), to_tf32(v.w));
    *(uint4*)dst = t;
}

__device__ __forceinline__ void b1fill(int c, char* dst, int tid) {
    #pragma unroll
    for (int i = 0; i < 4; i++) {
        int id = tid * 4 + i;            // 1024 granules of 16B
        int r = id >> 3, g8 = id & 7;
        cp16(dst + r * B1_STR + g8 * 16, (const char*)g_W1t + r * 2048 + c * 128 + g8 * 16);
    }
}
__device__ __forceinline__ void b2fill(int c, char* dst, int tid) {
    #pragma unroll
    for (int i = 0; i < 4; i++) {
        int id = tid * 4 + i;
        int r = id >> 3, g8 = id & 7;
        cp16(dst + r * B2_STR + g8 * 16, (const char*)g_W2t + r * 512 + c * 128 + g8 * 16);
    }
}

// ---------------- prep kernels ----------------
#define PB_Z   782
#define PB_W1  (PB_Z + 128)
#define PB_W2  (PB_W1 + 64)
#define PB_T   (PB_W2 + 8192)

__global__ void k_prep(const int* __restrict__ e,
                       const float* __restrict__ W1, const float* __restrict__ W2,
                       const float* __restrict__ bb, const float* __restrict__ seg) {
    int bx = blockIdx.x, tid = threadIdx.x;
    if (bx < PB_Z) {
        int i = bx * 256 + tid;
        if (i < NN) g_deg[i] = 0;
        if (bx == 0 && tid < 32) {
            int nz = (e[2 * tid + 1] != 0) ? 1 : 0;
            unsigned m = __ballot_sync(0xffffffffu, nz);
            if (tid == 0) { g_e64 = (m == 0u) ? 1 : 0; g_maxdeg = 0; }
        }
    } else if (bx < PB_W1) {
        int n = bx - PB_Z;
        #pragma unroll
        for (int it = 0; it < 2; it++) {
            int r = it * 256 + tid;
            int col;
            if      (r < CT)   col = r + 2;
            else if (r == 484) col = 0;
            else if (r == 485) col = 1;
            else if (r == 486) col = 486;
            else if (r == 487) col = 487;
            else               col = -1;
            float v = (col >= 0) ? W1[n * KIN + col] : 0.0f;
            g_W1t[n * 512 + permpos(r)] = __uint_as_float(to_tf32(v));
        }
    } else if (bx < PB_W2) {
        int n = (bx - PB_W1) * 2 + (tid >> 7), k = tid & 127;
        float v = W2[n * HID + k];
        g_W2t[n * 128 + permpos(k)] = __uint_as_float(to_tf32(v));
    } else {
        __shared__ float t[32][33];
        int i = bx - PB_W2;
        int c0 = (i & 15) * 32, p0 = (i >> 4) * 32;
        int tx = tid & 31, ty = tid >> 5;    // 32 x 8
        #pragma unroll
        for (int q = 0; q < 4; q++) {
            int c = c0 + ty + q * 8;
            float v = 0.0f;
            if (c < CT)
                v = (c < CBB) ? bb[(size_t)c * NPIX + p0 + tx]
                              : seg[(size_t)(c - CBB) * NPIX + p0 + tx];
            t[ty + q * 8][tx] = v;
        }
        __syncthreads();
        #pragma unroll
        for (int q = 0; q < 4; q++) {
            int p = p0 + ty + q * 8;
            int c = c0 + tx;
            if (c < CT) g_ft[(size_t)p * CT + c] = t[tx][ty + q * 8];
        }
    }
}

__global__ void k_degree(const void* __restrict__ eptr) {
    const int total = 2 * NEDGE;
    const bool is64 = (g_e64 != 0);
    const long long* __restrict__ e64 = (const long long*)eptr;
    const int* __restrict__ e32 = (const int*)eptr;
    for (int i = blockIdx.x * blockDim.x + threadIdx.x; i < total; i += gridDim.x * blockDim.x) {
        int idx = is64 ? (int)e64[i] : e32[i];
        atomicAdd(&g_deg[idx], 1);
    }
}

__global__ void k_max() {
    int i = blockIdx.x * blockDim.x + threadIdx.x;
    int v = (i < NN) ? g_deg[i] : 0;
    #pragma unroll
    for (int o = 16; o > 0; o >>= 1) v = max(v, __shfl_down_sync(0xffffffffu, v, o));
    if ((threadIdx.x & 31) == 0) atomicMax(&g_maxdeg, v);
}

// ---------------- main: float4 gather + tf32 mma.sync (permuted B, LDS.64 frags) ----------------
__global__ void __launch_bounds__(256, 2) k_main(
    const float* __restrict__ verts,
    const float* __restrict__ b1,
    const float* __restrict__ b2,
    float* __restrict__ out)
{
    extern __shared__ char smem[];
    int4*   Pq = (int4*)(smem + PQ_OFF);
    float4* Wq = (float4*)(smem + WQ_OFF);
    float4* Sq = (float4*)(smem + SQ_OFF);

    const int tid = threadIdx.x;
    const int m0 = blockIdx.x * 128;

    // per-node params
    if (tid < 128) {
        int node = min(m0 + tid, NN - 1);
        float vx = verts[2 * node], vy = verts[2 * node + 1];
        float ix = vx * (127.0f / 512.0f), iy = vy * (127.0f / 512.0f);
        float fx = floorf(ix), fy = floorf(iy);
        float wx = ix - fx, wy = iy - fy;
        int x0 = min(max((int)fx, 0), FDIM - 1);
        int x1 = min(x0 + 1, FDIM - 1);
        int y0 = min(max((int)fy, 0), FDIM - 1);
        int y1 = min(y0 + 1, FDIM - 1);
        Pq[tid] = make_int4((y0 * FDIM + x0) * CT, (y0 * FDIM + x1) * CT,
                            (y1 * FDIM + x0) * CT, (y1 * FDIM + x1) * CT);
        Wq[tid] = make_float4((1.0f - wx) * (1.0f - wy), wx * (1.0f - wy),
                              (1.0f - wx) * wy, wx * wy);
        float dg = (float)g_deg[node] / ((float)g_maxdeg + 1e-6f);
        float dx = fminf(vx, 512.0f - vx), dy = fminf(vy, 512.0f - vy);
        Sq[tid] = make_float4(vx * (1.0f / 512.0f), vy * (1.0f / 512.0f),
                              dg, fminf(dx, dy) * (1.0f / 256.0f));
    }
    __syncthreads();

    const int warp = tid >> 5, lane = tid & 31;
    const int g  = lane >> 2, tr = lane & 3, tc = tr * 2;
    const int wM = (warp & 3) * 32, wN = (warp >> 2) * 64;
    const int kq = tid & 7;               // builder k-quad
    const int ms = tid >> 3;              // builder m slot (0..31), m = ms*4 + s
    const int kofs = kq * 16;             // builder store byte offset

    float acc[2][8][4];
    #pragma unroll
    for (int a = 0; a < 2; a++)
        #pragma unroll
        for (int b = 0; b < 8; b++)
            #pragma unroll
            for (int c = 0; c < 4; c++) acc[a][b][c] = 0.0f;

    // -------- prologue: build A(0), fill B(0) --------
    b1fill(0, smem + B1_OFF(0), tid);
    CP_COMMIT();
    #pragma unroll
    for (int s = 0; s < 4; s++) {
        float4 f[4];
        int m = ms * 4 + s;
        bld_issue4(Pq, m, kq * 4, f);
        bld_store4(Wq, Sq, m, kq * 4, f, smem + A1_OFF(0) + m * A1_STR + kofs);
    }
    CP_WAIT0();
    __syncthreads();

    // ================= GEMM1: 16 chunks of 32 =================
    #pragma unroll 1
    for (int c = 0; c < 16; c++) {
        const char* A = smem + A1_OFF(c & 1);
        const char* B = smem + B1_OFF(c & 1);
        char* nA = smem + A1_OFF((c + 1) & 1);
        const bool more = (c < 15);

        if (more) b1fill(c + 1, smem + B1_OFF((c + 1) & 1), tid);
        else      b2fill(0, smem + B2_OFF, tid);        // prefetch W2 chunk 0
        CP_COMMIT();

        const int k0n = (c + 1) * 32 + kq * 4;
        #pragma unroll
        for (int s = 0; s < 4; s++) {                   // k8 segments; builder batch = s
            float4 f[4];
            const int mB = ms * 4 + s;
            if (more) bld_issue4(Pq, mB, k0n, f);

            uint32_t a0[4], a1[4];
            ldA(a0, A, wM + g,      s * 8 + tr, A1_STR);
            ldA(a1, A, wM + 16 + g, s * 8 + tr, A1_STR);
            #pragma unroll
            for (int nb = 0; nb < 8; nb++) {
                uint2 bfr = *(const uint2*)(B + (wN + nb * 8 + g) * B1_STR + s * 32 + tr * 8);
                mma_tf32(acc[0][nb], a0, bfr.x, bfr.y);
                mma_tf32(acc[1][nb], a1, bfr.x, bfr.y);
            }
            if (more) bld_store4(Wq, Sq, mB, k0n, f, nA + mB * A1_STR + kofs);
        }
        CP_WAIT0();
        __syncthreads();
    }

    // -------- epilogue 1: h1 = relu(D1 + b1) -> tf32 smem tile A2 --------
    {
        char* A2 = smem + A2_OFF;
        #pragma unroll
        for (int mb = 0; mb < 2; mb++) {
            int row = wM + mb * 16 + g;
            #pragma unroll
            for (int nb = 0; nb < 8; nb++) {
                int col = wN + nb * 8 + tc;
                float2 bb = *(const float2*)(b1 + col);
                float v0 = fmaxf(acc[mb][nb][0] + bb.x, 0.0f);
                float v1 = fmaxf(acc[mb][nb][1] + bb.y, 0.0f);
                float v2 = fmaxf(acc[mb][nb][2] + bb.x, 0.0f);
                float v3 = fmaxf(acc[mb][nb][3] + bb.y, 0.0f);
                *(uint2*)(A2 + row * A2_STR + col * 4)       = make_uint2(to_tf32(v0), to_tf32(v1));
                *(uint2*)(A2 + (row + 8) * A2_STR + col * 4) = make_uint2(to_tf32(v2), to_tf32(v3));
            }
        }
    }
    #pragma unroll
    for (int a = 0; a < 2; a++)
        #pragma unroll
        for (int b = 0; b < 8; b++)
            #pragma unroll
            for (int c = 0; c < 4; c++) acc[a][b][c] = 0.0f;
    __syncthreads();

    // ================= GEMM2: 4 chunks of 32 (single B2 buffer, prefetched) =================
    #pragma unroll 1
    for (int c2 = 0; c2 < 4; c2++) {
        const char* A2 = smem + A2_OFF;
        const char* B = smem + B2_OFF;
        #pragma unroll
        for (int s = 0; s < 4; s++) {
            uint32_t a0[4], a1[4];
            int col = c2 * 32 + s * 8 + tr;
            ldA(a0, A2, wM + g,      col, A2_STR);
            ldA(a1, A2, wM + 16 + g, col, A2_STR);
            #pragma unroll
            for (int nb = 0; nb < 8; nb++) {
                uint2 bfr = *(const uint2*)(B + (wN + nb * 8 + g) * B2_STR + s * 32 + tr * 8);
                mma_tf32(acc[0][nb], a0, bfr.x, bfr.y);
                mma_tf32(acc[1][nb], a1, bfr.x, bfr.y);
            }
        }
        if (c2 < 3) {
            __syncthreads();                 // all reads of B2 done
            b2fill(c2 + 1, smem + B2_OFF, tid);
            CP_COMMIT(); CP_WAIT0();
            __syncthreads();
        }
    }

    // -------- epilogue 2: out = relu(D2 + b2) --------
    #pragma unroll
    for (int mb = 0; mb < 2; mb++) {
        int m1 = m0 + wM + mb * 16 + g;
        int m2 = m1 + 8;
        #pragma unroll
        for (int nb = 0; nb < 8; nb++) {
            int col = wN + nb * 8 + tc;
            float2 bb = *(const float2*)(b2 + col);
            if (m1 < NN) {
                float2 v = make_float2(fmaxf(acc[mb][nb][0] + bb.x, 0.0f),
                                       fmaxf(acc[mb][nb][1] + bb.y, 0.0f));
                *(float2*)(out + (size_t)m1 * HID + col) = v;
            }
            if (m2 < NN) {
                float2 v = make_float2(fmaxf(acc[mb][nb][2] + bb.x, 0.0f),
                                       fmaxf(acc[mb][nb][3] + bb.y, 0.0f));
                *(float2*)(out + (size_t)m2 * HID + col) = v;
            }
        }
    }
}

// ---------------- launch ----------------
extern "C" void kernel_launch(void* const* d_in, const int* in_sizes, int n_in,
                              void* d_out, int out_size)
{
    const float* verts = (const float*)d_in[0];
    const float* bb    = (const float*)d_in[1];
    const float* seg   = (const float*)d_in[2];
    const void*  edges = d_in[3];
    const float* W1    = (const float*)d_in[4];
    const float* b1    = (const float*)d_in[5];
    const float* W2    = (const float*)d_in[6];
    const float* b2    = (const float*)d_in[7];
    float* out = (float*)d_out;

    k_prep<<<PB_T, 256>>>((const int*)edges, W1, W2, bb, seg);
    k_degree<<<2048, 256>>>(edges);
    k_max<<<(NN + 255) / 256, 256>>>();

    cudaFuncSetAttribute(k_main, cudaFuncAttributeMaxDynamicSharedMemorySize, SMEM_BYTES);
    k_main<<<(NN + 127) / 128, 256, SMEM_BYTES>>>(verts, b1, b2, out);
}